// round 1
// baseline (speedup 1.0000x reference)
#include <cuda_runtime.h>

// EMA with bias correction, fused single pass.
// x: (32, 256, 8192) f32 -> 8192 rows of T=8192.
// y[t] = 0.99*y[t-1] + 0.01*x[t];  out[t] = y[t] / (1 - 0.99^(t+1))

#define T_LEN   8192
#define THREADS 256
#define PER     32     // elements per thread (one 128B line)

__device__ float g_corr[2048];

__global__ void init_corr_kernel() {
    int t = blockIdx.x * blockDim.x + threadIdx.x;
    if (t < 2048) {
        double q = pow(0.99, (double)(t + 1));
        g_corr[t] = (float)(1.0 / (1.0 - q));
    }
}

__global__ __launch_bounds__(THREADS)
void ema_kernel(const float* __restrict__ x, float* __restrict__ out) {
    const int row  = blockIdx.x;
    const int tid  = threadIdx.x;
    const int lane = tid & 31;
    const int warp = tid >> 5;

    const float OM = 0.99f;
    const float M  = 0.01f;

    const size_t base = (size_t)row * T_LEN + (size_t)tid * PER;
    const float4* __restrict__ p = (const float4*)(x + base);

    // Load this thread's 128B line (8 x LDG.128, MLP=8)
    float xv[PER];
#pragma unroll
    for (int i = 0; i < 8; i++) {
        float4 v = p[i];
        xv[4*i + 0] = v.x; xv[4*i + 1] = v.y;
        xv[4*i + 2] = v.z; xv[4*i + 3] = v.w;
    }

    // Local inclusive EMA seeded from 0: b-part of affine composition
    float s = 0.0f;
#pragma unroll
    for (int k = 0; k < PER; k++)
        s = fmaf(OM, s, M * xv[k]);

    // A = 0.99^32 (a-part of each thread's 32-element segment)
    float A = OM;
#pragma unroll
    for (int i = 0; i < 5; i++) A = A * A;

    // Warp-inclusive scan of affine pairs (aa, s):
    // combine(prev, cur): b = a_cur*b_prev + b_cur ; a = a_prev*a_cur
    float aa = A;
#pragma unroll
    for (int d = 1; d < 32; d <<= 1) {
        float ap = __shfl_up_sync(0xffffffffu, aa, d);
        float sp = __shfl_up_sync(0xffffffffu, s,  d);
        if (lane >= d) {
            s  = fmaf(aa, sp, s);
            aa = aa * ap;
        }
    }

    // Exclusive within warp
    float eb = __shfl_up_sync(0xffffffffu, s,  1);
    float ea = __shfl_up_sync(0xffffffffu, aa, 1);
    if (lane == 0) { eb = 0.0f; ea = 1.0f; }

    __shared__ float wsum[THREADS / 32];
    if (lane == 31) wsum[warp] = s;   // inclusive b over this warp's 1024 elems
    __syncthreads();

    // AW = A^32 = 0.99^1024
    float AW = A;
#pragma unroll
    for (int i = 0; i < 5; i++) AW = AW * AW;

    // Carry into this warp = ordered combine of prior warp totals
    float cw = 0.0f;
#pragma unroll
    for (int j = 0; j < THREADS / 32; j++) {
        if (j < warp) cw = fmaf(AW, cw, wsum[j]);
    }

    // Carry into this thread's chunk
    float carry = fmaf(ea, cw, eb);

    // Second pass: seeded recurrence reproduces exact y; apply corr; store.
    float4* __restrict__ po = (float4*)(out + base);
    float c = carry;

    if (tid < 64) {
        // t = tid*32 + k < 2048: bias correction != 1.0f
        const float4* __restrict__ cp = (const float4*)(g_corr + tid * PER);
#pragma unroll
        for (int i = 0; i < 8; i++) {
            float4 cr = cp[i];
            float4 w;
            c = fmaf(OM, c, M * xv[4*i + 0]); w.x = c * cr.x;
            c = fmaf(OM, c, M * xv[4*i + 1]); w.y = c * cr.y;
            c = fmaf(OM, c, M * xv[4*i + 2]); w.z = c * cr.z;
            c = fmaf(OM, c, M * xv[4*i + 3]); w.w = c * cr.w;
            po[i] = w;
        }
    } else {
        // t >= 2048: 0.99^(t+1) < 2^-25, fp32 corr == 1.0 exactly
#pragma unroll
        for (int i = 0; i < 8; i++) {
            float4 w;
            c = fmaf(OM, c, M * xv[4*i + 0]); w.x = c;
            c = fmaf(OM, c, M * xv[4*i + 1]); w.y = c;
            c = fmaf(OM, c, M * xv[4*i + 2]); w.z = c;
            c = fmaf(OM, c, M * xv[4*i + 3]); w.w = c;
            po[i] = w;
        }
    }
}

extern "C" void kernel_launch(void* const* d_in, const int* in_sizes, int n_in,
                              void* d_out, int out_size) {
    const float* x = (const float*)d_in[0];
    float* out = (float*)d_out;

    int rows = in_sizes[0] / T_LEN;   // 8192

    init_corr_kernel<<<8, 256>>>();
    ema_kernel<<<rows, THREADS>>>(x, out);
}

// round 2
// speedup vs baseline: 1.7087x; 1.7087x over previous
#include <cuda_runtime.h>

// EMA with bias correction, fused single pass, fully coalesced.
// x: (32, 256, 8192) f32 -> 8192 rows of T=8192.
// y[t] = 0.99*y[t-1] + 0.01*x[t];  out[t] = y[t] / (1 - 0.99^(t+1))
//
// Layout: block = row (256 thr, 8 warps). Warp w owns elements [w*1024, w*1024+1024).
// Lane l holds 8 groups of 4 contiguous floats at offset i*128 + l*4 (i=0..7)
// -> every LDG.128 / STG.128 is warp-coalesced (4 lines / instruction).

#define T_LEN   8192
#define THREADS 256

__device__ float g_corr[2048];

__global__ void init_corr_kernel() {
    int t = blockIdx.x * blockDim.x + threadIdx.x;
    if (t < 2048) {
        double q = pow(0.99, (double)(t + 1));
        g_corr[t] = (float)(1.0 / (1.0 - q));
    }
}

__global__ __launch_bounds__(THREADS)
void ema_kernel(const float* __restrict__ x, float* __restrict__ out) {
    const int row  = blockIdx.x;
    const int tid  = threadIdx.x;
    const int lane = tid & 31;
    const int warp = tid >> 5;

    const float OM = 0.99f;
    const float M  = 0.01f;

    // Compile-time decay constants
    const float A4_1  = OM * OM * OM * OM;    // 0.99^4
    const float A4_2  = A4_1  * A4_1;         // 0.99^8
    const float A4_4  = A4_2  * A4_2;         // 0.99^16
    const float A4_8  = A4_4  * A4_4;         // 0.99^32
    const float A4_16 = A4_8  * A4_8;         // 0.99^64
    const float A128  = A4_16 * A4_16;        // 0.99^128
    const float A256  = A128  * A128;
    const float A512  = A256  * A256;
    const float A1024 = A512  * A512;         // 0.99^1024

    // Base: this lane's first group within its warp's 1024-element segment
    const size_t base = (size_t)row * T_LEN + (size_t)warp * 1024 + (size_t)lane * 4;
    const float4* __restrict__ p = (const float4*)(x + base);

    // Coalesced loads: group i at +i*128 floats (= +32 float4)
    float4 v[8];
#pragma unroll
    for (int i = 0; i < 8; i++) v[i] = p[i * 32];

    // Level 1: serial affine over each 4-group (seeded from 0) -> b4
    float bb[8];
#pragma unroll
    for (int i = 0; i < 8; i++) {
        float s;
        s = M * v[i].x;
        s = fmaf(OM, s, M * v[i].y);
        s = fmaf(OM, s, M * v[i].z);
        s = fmaf(OM, s, M * v[i].w);
        bb[i] = s;
    }

    // Level 2: per-i warp inclusive scan over lanes.
    // Decay per lane is uniform (A4), so only b needs scanning:
    //   stage d: bb_l = A4^d * bb_{l-d} + bb_l   (for l >= d)
    float excl[8], b128[8];
#pragma unroll
    for (int i = 0; i < 8; i++) {
        float b = bb[i];
        float t1 = __shfl_up_sync(0xffffffffu, b, 1);
        if (lane >= 1)  b = fmaf(A4_1,  t1, b);
        float t2 = __shfl_up_sync(0xffffffffu, b, 2);
        if (lane >= 2)  b = fmaf(A4_2,  t2, b);
        float t4 = __shfl_up_sync(0xffffffffu, b, 4);
        if (lane >= 4)  b = fmaf(A4_4,  t4, b);
        float t8 = __shfl_up_sync(0xffffffffu, b, 8);
        if (lane >= 8)  b = fmaf(A4_8,  t8, b);
        float t16 = __shfl_up_sync(0xffffffffu, b, 16);
        if (lane >= 16) b = fmaf(A4_16, t16, b);

        float e = __shfl_up_sync(0xffffffffu, b, 1);
        excl[i] = (lane == 0) ? 0.0f : e;          // carry into lane l within block i
        b128[i] = __shfl_sync(0xffffffffu, b, 31); // block-i total
    }

    // Warp total over its 1024 elements: chain the 8 block totals
    float tot = b128[0];
#pragma unroll
    for (int i = 1; i < 8; i++) tot = fmaf(A128, tot, b128[i]);

    __shared__ float wsum[THREADS / 32];
    if (lane == 0) wsum[warp] = tot;
    __syncthreads();

    // Carry into this warp: ordered combine of prior warp totals
    float cw = 0.0f;
#pragma unroll
    for (int j = 0; j < THREADS / 32; j++) {
        if (j < warp) cw = fmaf(A1024, cw, wsum[j]);
    }

    // Lane decay 0.99^(4*lane) via binary products of constants
    float al = (lane & 1) ? A4_1 : 1.0f;
    if (lane & 2)  al *= A4_2;
    if (lane & 4)  al *= A4_4;
    if (lane & 8)  al *= A4_8;
    if (lane & 16) al *= A4_16;

    float4* __restrict__ po = (float4*)(out + base);

    if (warp < 2) {
        // global t = warp*1024 + i*128 + lane*4 + j < 2048: apply correction
        const float4* __restrict__ cp =
            (const float4*)(g_corr + warp * 1024 + lane * 4);
        float c = cw;  // carry into block i
#pragma unroll
        for (int i = 0; i < 8; i++) {
            float cc = fmaf(al, c, excl[i]);  // carry into this lane's group
            float4 cr = cp[i * 32];
            float4 w;
            cc = fmaf(OM, cc, M * v[i].x); w.x = cc * cr.x;
            cc = fmaf(OM, cc, M * v[i].y); w.y = cc * cr.y;
            cc = fmaf(OM, cc, M * v[i].z); w.z = cc * cr.z;
            cc = fmaf(OM, cc, M * v[i].w); w.w = cc * cr.w;
            po[i * 32] = w;
            c = fmaf(A128, c, b128[i]);       // carry into next block
        }
    } else {
        // t >= 2048: 0.99^(t+1) < 2^-25 -> fp32 corr == 1.0 exactly
        float c = cw;
#pragma unroll
        for (int i = 0; i < 8; i++) {
            float cc = fmaf(al, c, excl[i]);
            float4 w;
            cc = fmaf(OM, cc, M * v[i].x); w.x = cc;
            cc = fmaf(OM, cc, M * v[i].y); w.y = cc;
            cc = fmaf(OM, cc, M * v[i].z); w.z = cc;
            cc = fmaf(OM, cc, M * v[i].w); w.w = cc;
            po[i * 32] = w;
            c = fmaf(A128, c, b128[i]);
        }
    }
}

extern "C" void kernel_launch(void* const* d_in, const int* in_sizes, int n_in,
                              void* d_out, int out_size) {
    const float* x = (const float*)d_in[0];
    float* out = (float*)d_out;

    int rows = in_sizes[0] / T_LEN;   // 8192

    init_corr_kernel<<<8, 256>>>();
    ema_kernel<<<rows, THREADS>>>(x, out);
}

// round 3
// speedup vs baseline: 1.8794x; 1.0999x over previous
#include <cuda_runtime.h>

// EMA with bias correction, single fused kernel, fully coalesced.
// x: (32, 256, 8192) f32 -> 8192 rows of T=8192.
// y[t] = 0.99*y[t-1] + 0.01*x[t];  out[t] = y[t] / (1 - 0.99^(t+1))
//
// Layout: block = row (256 thr, 8 warps). Warp w owns elements [w*1024, (w+1)*1024).
// Lane l holds 8 groups of 4 contiguous floats at offset i*128 + l*4 (i=0..7)
// -> every LDG.128 / STG.128 is warp-coalesced.
//
// Bias correction: for t >= 2048, 0.99^(t+1) < 2^-25 so fp32 corr == 1.0 exactly
// (warps 2..7 skip it). Warps 0-1 compute corr inline: q = 0.99^(t+1) built from
// exact compile-time constant products + a 4-step in-group recurrence, then one
// fast reciprocal per element (MUFU, fully hidden under memory).

#define T_LEN   8192
#define THREADS 256

__global__ __launch_bounds__(THREADS)
void ema_kernel(const float* __restrict__ x, float* __restrict__ out) {
    const int row  = blockIdx.x;
    const int tid  = threadIdx.x;
    const int lane = tid & 31;
    const int warp = tid >> 5;

    const float OM = 0.99f;
    const float M  = 0.01f;

    // Compile-time decay constants
    const float A4_1  = OM * OM * OM * OM;    // 0.99^4
    const float A4_2  = A4_1  * A4_1;         // 0.99^8
    const float A4_4  = A4_2  * A4_2;         // 0.99^16
    const float A4_8  = A4_4  * A4_4;         // 0.99^32
    const float A4_16 = A4_8  * A4_8;         // 0.99^64
    const float A128  = A4_16 * A4_16;        // 0.99^128
    const float A256  = A128  * A128;
    const float A512  = A256  * A256;
    const float A1024 = A512  * A512;         // 0.99^1024

    // Base: this lane's first group within its warp's 1024-element segment
    const size_t base = (size_t)row * T_LEN + (size_t)warp * 1024 + (size_t)lane * 4;
    const float4* __restrict__ p = (const float4*)(x + base);

    // Coalesced streaming loads: group i at +i*128 floats (= +32 float4)
    float4 v[8];
#pragma unroll
    for (int i = 0; i < 8; i++) v[i] = __ldcs(p + i * 32);

    // Level 1: serial affine over each 4-group (seeded from 0) -> b4
    float bb[8];
#pragma unroll
    for (int i = 0; i < 8; i++) {
        float s;
        s = M * v[i].x;
        s = fmaf(OM, s, M * v[i].y);
        s = fmaf(OM, s, M * v[i].z);
        s = fmaf(OM, s, M * v[i].w);
        bb[i] = s;
    }

    // Level 2: per-i warp inclusive scan over lanes.
    // Decay per lane is uniform (A4), so only b needs scanning:
    //   stage d: bb_l = A4^d * bb_{l-d} + bb_l   (for l >= d)
    float excl[8], b128[8];
#pragma unroll
    for (int i = 0; i < 8; i++) {
        float b = bb[i];
        float t1 = __shfl_up_sync(0xffffffffu, b, 1);
        if (lane >= 1)  b = fmaf(A4_1,  t1, b);
        float t2 = __shfl_up_sync(0xffffffffu, b, 2);
        if (lane >= 2)  b = fmaf(A4_2,  t2, b);
        float t4 = __shfl_up_sync(0xffffffffu, b, 4);
        if (lane >= 4)  b = fmaf(A4_4,  t4, b);
        float t8 = __shfl_up_sync(0xffffffffu, b, 8);
        if (lane >= 8)  b = fmaf(A4_8,  t8, b);
        float t16 = __shfl_up_sync(0xffffffffu, b, 16);
        if (lane >= 16) b = fmaf(A4_16, t16, b);

        float e = __shfl_up_sync(0xffffffffu, b, 1);
        excl[i] = (lane == 0) ? 0.0f : e;          // carry into lane l within block i
        b128[i] = __shfl_sync(0xffffffffu, b, 31); // block-i total
    }

    // Warp total over its 1024 elements: chain the 8 block totals
    float tot = b128[0];
#pragma unroll
    for (int i = 1; i < 8; i++) tot = fmaf(A128, tot, b128[i]);

    __shared__ float wsum[THREADS / 32];
    if (lane == 0) wsum[warp] = tot;
    __syncthreads();

    // Carry into this warp: ordered combine of prior warp totals
    float cw = 0.0f;
#pragma unroll
    for (int j = 0; j < THREADS / 32; j++) {
        if (j < warp) cw = fmaf(A1024, cw, wsum[j]);
    }

    // Lane decay 0.99^(4*lane) via binary products of constants
    float al = (lane & 1) ? A4_1 : 1.0f;
    if (lane & 2)  al *= A4_2;
    if (lane & 4)  al *= A4_4;
    if (lane & 8)  al *= A4_8;
    if (lane & 16) al *= A4_16;

    float4* __restrict__ po = (float4*)(out + base);

    if (warp < 2) {
        // global t = warp*1024 + i*128 + lane*4 + j < 2048: apply correction.
        // q at this lane's (i=0, j=0) element: 0.99^(warp*1024 + lane*4 + 1)
        float qb = OM * al;
        if (warp == 1) qb *= A1024;

        float c = cw;  // carry into block i (at lane 0 position)
#pragma unroll
        for (int i = 0; i < 8; i++) {
            float cc = fmaf(al, c, excl[i]);  // carry into this lane's group
            float q = qb;
            float4 w;
            cc = fmaf(OM, cc, M * v[i].x); w.x = __fdividef(cc, 1.0f - q); q *= OM;
            cc = fmaf(OM, cc, M * v[i].y); w.y = __fdividef(cc, 1.0f - q); q *= OM;
            cc = fmaf(OM, cc, M * v[i].z); w.z = __fdividef(cc, 1.0f - q); q *= OM;
            cc = fmaf(OM, cc, M * v[i].w); w.w = __fdividef(cc, 1.0f - q);
            __stcs(po + i * 32, w);
            c  = fmaf(A128, c, b128[i]);      // carry into next block
            qb *= A128;
        }
    } else {
        // t >= 2048: corr == 1.0f exactly in fp32
        float c = cw;
#pragma unroll
        for (int i = 0; i < 8; i++) {
            float cc = fmaf(al, c, excl[i]);
            float4 w;
            cc = fmaf(OM, cc, M * v[i].x); w.x = cc;
            cc = fmaf(OM, cc, M * v[i].y); w.y = cc;
            cc = fmaf(OM, cc, M * v[i].z); w.z = cc;
            cc = fmaf(OM, cc, M * v[i].w); w.w = cc;
            __stcs(po + i * 32, w);
            c = fmaf(A128, c, b128[i]);
        }
    }
}

extern "C" void kernel_launch(void* const* d_in, const int* in_sizes, int n_in,
                              void* d_out, int out_size) {
    const float* x = (const float*)d_in[0];
    float* out = (float*)d_out;

    int rows = in_sizes[0] / T_LEN;   // 8192

    ema_kernel<<<rows, THREADS>>>(x, out);
}